// round 14
// baseline (speedup 1.0000x reference)
#include <cuda_runtime.h>
#include <cstdint>

typedef unsigned long long u64;

#define B_ 32
#define N_ 64
#define D_ 256
#define C_ 8192
#define KSPLIT 4

// Scratch (static device memory — no runtime allocation).
__device__ float g_q1p[KSPLIT][(size_t)B_ * N_ * D_]; // K-split partials, 8 MB
__device__ unsigned g_Wh[(size_t)D_ * (C_ / 2)];      // W hi bf16x2, 4 MB
__device__ unsigned g_Wl[(size_t)D_ * (C_ / 2)];      // W lo bf16x2, 4 MB
__device__ unsigned g_zh[(size_t)B_ * N_ * (C_ / 2)]; // z hi bf16x2, 32 MB
__device__ unsigned g_zl[(size_t)B_ * N_ * (C_ / 2)]; // z lo bf16x2, 32 MB

// ---------- packed f32x2 helpers (posmap) ----------
__device__ __forceinline__ u64 splat2(float x) {
    u64 r; unsigned xi = __float_as_uint(x);
    asm("mov.b64 %0, {%1, %1};" : "=l"(r) : "r"(xi));
    return r;
}
__device__ __forceinline__ void ffma2(u64 &d, u64 a, u64 b) {
    asm("fma.rn.f32x2 %0, %1, %2, %0;" : "+l"(d) : "l"(a), "l"(b));
}
__device__ __forceinline__ float2 unpack2(u64 v) {
    unsigned lo, hi;
    asm("mov.b64 {%0, %1}, %2;" : "=r"(lo), "=r"(hi) : "l"(v));
    return make_float2(__uint_as_float(lo), __uint_as_float(hi));
}

// ---------- bf16 split: (x,y) -> packed hi bf16x2 + packed lo bf16x2 ----------
__device__ __forceinline__ void bsplit2(float x, float y, unsigned &h, unsigned &l) {
    unsigned hp;
    asm("cvt.rn.bf16x2.f32 %0, %1, %2;" : "=r"(hp) : "f"(y), "f"(x));
    float hx = __uint_as_float(hp << 16);
    float hy = __uint_as_float(hp & 0xFFFF0000u);
    asm("cvt.rn.bf16x2.f32 %0, %1, %2;" : "=r"(l) : "f"(y - hy), "f"(x - hx));
    h = hp;
}

// D += A@B, m16n8k16 bf16
__device__ __forceinline__ void mma16(float* d, const unsigned* a, const unsigned* b) {
    asm volatile(
        "mma.sync.aligned.m16n8k16.row.col.f32.bf16.bf16.f32 "
        "{%0,%1,%2,%3}, {%4,%5,%6,%7}, {%8,%9}, {%0,%1,%2,%3};"
        : "+f"(d[0]), "+f"(d[1]), "+f"(d[2]), "+f"(d[3])
        : "r"(a[0]), "r"(a[1]), "r"(a[2]), "r"(a[3]), "r"(b[0]), "r"(b[1]));
}

// ---------- smem / ldmatrix / cp.async ----------
__device__ __forceinline__ unsigned sptr(const void* p) {
    return (unsigned)__cvta_generic_to_shared(p);
}
__device__ __forceinline__ void ldsm4(unsigned* r, unsigned addr) {
    asm volatile("ldmatrix.sync.aligned.m8n8.x4.shared.b16 {%0,%1,%2,%3}, [%4];"
                 : "=r"(r[0]), "=r"(r[1]), "=r"(r[2]), "=r"(r[3]) : "r"(addr));
}
__device__ __forceinline__ void ldsm4t(unsigned* r, unsigned addr) {
    asm volatile("ldmatrix.sync.aligned.m8n8.x4.trans.shared.b16 {%0,%1,%2,%3}, [%4];"
                 : "=r"(r[0]), "=r"(r[1]), "=r"(r[2]), "=r"(r[3]) : "r"(addr));
}
__device__ __forceinline__ void cpa16(unsigned dst, const void* src) {
    asm volatile("cp.async.cg.shared.global [%0], [%1], 16;" :: "r"(dst), "l"(src) : "memory");
}

// ============ Kernel 1: la[b,n,c] = sum_k logits[b,n,k] * head[n,k,c] ============
// Grid (32, 65): blockIdx.y < 64 -> GEMM tile; blockIdx.y == 64 -> W pre-split.
// GEMM: bf16 3-pass split (hh+hl+lh), pass-major MMA order, ldmatrix fragments,
// register-prefetch double-buffered staging. Block 256 (8 warps: 2m x 4n;
// warp tile 16x64). K=256, chunks of 32.
// stage u32 layout: Ah[32*20]@0, Al@640, Bh[32*132]@1280, Bl@5504; stage = 9728 u32.
#define G1_STAGE 9728
#define G1_SMEM_BYTES (2 * G1_STAGE * 4)
__global__ __launch_bounds__(256, 2) void k_gemm_head_mma(
    const float* __restrict__ logits, const float* __restrict__ head,
    const float* __restrict__ W, float* __restrict__ la)
{
    extern __shared__ __align__(16) unsigned sm1[];
    const int tid = threadIdx.x;

    if (blockIdx.y == N_) {
        // W pre-split plane: 32 CTAs x 256 thr x 64 float4 = 8 MB
        #pragma unroll 4
        for (int it = 0; it < 64; it++) {
            size_t i = (size_t)blockIdx.x * 16384 + (size_t)it * 256 + tid;
            float4 v = *reinterpret_cast<const float4*>(&W[i * 4]);
            unsigned h0, l0, h1, l1;
            bsplit2(v.x, v.y, h0, l0);
            bsplit2(v.z, v.w, h1, l1);
            g_Wh[i * 2] = h0; g_Wh[i * 2 + 1] = h1;
            g_Wl[i * 2] = l0; g_Wl[i * 2 + 1] = l1;
        }
        return;
    }

    const int n  = blockIdx.y;
    const int c0 = blockIdx.x * 256;
    const int wid = tid >> 5, lane = tid & 31;
    const int g = lane >> 2, tig = lane & 3;
    const int wm = wid & 1, wn = wid >> 1;
    const int ra = tid >> 3, qa = tid & 7;
    const int l16 = lane & 15, lh = lane >> 4;

    float acc[8][4];
    #pragma unroll
    for (int i = 0; i < 8; i++)
        #pragma unroll
        for (int j = 0; j < 4; j++) acc[i][j] = 0.0f;

    // prologue: load + stage chunk 0 into buffer 0
    {
        float4 va = *reinterpret_cast<const float4*>(
            &logits[((size_t)ra * N_ + n) * D_ + 4 * qa]);
        unsigned* Ah = sm1;
        unsigned* Al = sm1 + 640;
        unsigned* Bh = sm1 + 1280;
        unsigned* Bl = sm1 + 5504;
        unsigned h0, l0, h1, l1;
        bsplit2(va.x, va.y, h0, l0); bsplit2(va.z, va.w, h1, l1);
        *reinterpret_cast<uint2*>(&Ah[ra * 20 + 2 * qa]) = make_uint2(h0, h1);
        *reinterpret_cast<uint2*>(&Al[ra * 20 + 2 * qa]) = make_uint2(l0, l1);
        #pragma unroll
        for (int it = 0; it < 8; it++) {
            int i = tid + it * 256;
            int k = i >> 6, c4 = i & 63;
            float4 v = *reinterpret_cast<const float4*>(
                &head[((size_t)n * D_ + k) * C_ + c0 + 4 * c4]);
            bsplit2(v.x, v.y, h0, l0); bsplit2(v.z, v.w, h1, l1);
            *reinterpret_cast<uint2*>(&Bh[k * 132 + 2 * c4]) = make_uint2(h0, h1);
            *reinterpret_cast<uint2*>(&Bl[k * 132 + 2 * c4]) = make_uint2(l0, l1);
        }
    }
    __syncthreads();

    for (int ch = 0; ch < 8; ch++) {
        float4 va; float4 vb[8];
        if (ch < 7) {
            const int kb = (ch + 1) * 32;
            va = *reinterpret_cast<const float4*>(
                &logits[((size_t)ra * N_ + n) * D_ + kb + 4 * qa]);
            #pragma unroll
            for (int it = 0; it < 8; it++) {
                int i = tid + it * 256;
                int k = i >> 6, c4 = i & 63;
                vb[it] = *reinterpret_cast<const float4*>(
                    &head[((size_t)n * D_ + kb + k) * C_ + c0 + 4 * c4]);
            }
        }

        unsigned* st = sm1 + (ch & 1) * G1_STAGE;
        unsigned* Ah = st;
        unsigned* Al = st + 640;
        unsigned* Bh = st + 1280;
        unsigned* Bl = st + 5504;

        #pragma unroll
        for (int s = 0; s < 2; s++) {
            unsigned ah[4], al[4];
            const int aoff = (wm * 16 + l16) * 20 + s * 8 + lh * 4;
            ldsm4(ah, sptr(Ah + aoff));
            ldsm4(al, sptr(Al + aoff));
            unsigned bfh[4][4], bfl[4][4];
            #pragma unroll
            for (int p = 0; p < 4; p++) {
                const int boff = (s * 16 + l16) * 132 + wn * 32 + p * 8 + lh * 4;
                ldsm4t(bfh[p], sptr(Bh + boff));
                ldsm4t(bfl[p], sptr(Bl + boff));
            }
            #pragma unroll
            for (int p = 0; p < 4; p++) {
                mma16(acc[2 * p],     ah, &bfh[p][0]);
                mma16(acc[2 * p + 1], ah, &bfh[p][2]);
            }
            #pragma unroll
            for (int p = 0; p < 4; p++) {
                mma16(acc[2 * p],     ah, &bfl[p][0]);
                mma16(acc[2 * p + 1], ah, &bfl[p][2]);
            }
            #pragma unroll
            for (int p = 0; p < 4; p++) {
                mma16(acc[2 * p],     al, &bfh[p][0]);
                mma16(acc[2 * p + 1], al, &bfh[p][2]);
            }
        }

        if (ch < 7) {
            unsigned* nx = sm1 + ((ch + 1) & 1) * G1_STAGE;
            unsigned* nAh = nx;
            unsigned* nAl = nx + 640;
            unsigned* nBh = nx + 1280;
            unsigned* nBl = nx + 5504;
            unsigned h0, l0, h1, l1;
            bsplit2(va.x, va.y, h0, l0); bsplit2(va.z, va.w, h1, l1);
            *reinterpret_cast<uint2*>(&nAh[ra * 20 + 2 * qa]) = make_uint2(h0, h1);
            *reinterpret_cast<uint2*>(&nAl[ra * 20 + 2 * qa]) = make_uint2(l0, l1);
            #pragma unroll
            for (int it = 0; it < 8; it++) {
                int i = tid + it * 256;
                int k = i >> 6, c4 = i & 63;
                bsplit2(vb[it].x, vb[it].y, h0, l0);
                bsplit2(vb[it].z, vb[it].w, h1, l1);
                *reinterpret_cast<uint2*>(&nBh[k * 132 + 2 * c4]) = make_uint2(h0, h1);
                *reinterpret_cast<uint2*>(&nBl[k * 132 + 2 * c4]) = make_uint2(l0, l1);
            }
        }
        __syncthreads();
    }

    const int r = wm * 16 + g;
    #pragma unroll
    for (int nf = 0; nf < 8; nf++) {
        int c = c0 + wn * 64 + nf * 8 + 2 * tig;
        size_t b1 = ((size_t)r * N_ + n) * C_ + c;
        size_t b2 = ((size_t)(r + 8) * N_ + n) * C_ + c;
        *reinterpret_cast<float2*>(&la[b1]) = make_float2(acc[nf][0], acc[nf][1]);
        *reinterpret_cast<float2*>(&la[b2]) = make_float2(acc[nf][2], acc[nf][3]);
    }
}

// ============ Kernel 2: z = softmax((la + gum)/tau); also emit bf16 hi/lo planes ============
// Launched twice with a row offset (profiling-position control; rows independent).
__global__ __launch_bounds__(256) void k_softmax(
    const float* __restrict__ la, const float* __restrict__ gum,
    const float* __restrict__ tau, float* __restrict__ z, int m0)
{
    __shared__ __align__(16) float sv[C_];
    __shared__ float redm[8];
    __shared__ float reds[8];
    const int m = m0 + blockIdx.x;
    const size_t base = (size_t)m * C_;
    const float inv_tau = 1.0f / tau[0];
    const int tid = threadIdx.x;
    const int w = tid >> 5, l = tid & 31;

    float lmax = -3.4e38f;
    for (int c = tid * 4; c < C_; c += 1024) {
        float4 a = *reinterpret_cast<const float4*>(&la[base + c]);
        float4 g = *reinterpret_cast<const float4*>(&gum[base + c]);
        float4 v;
        v.x = (a.x + g.x) * inv_tau;
        v.y = (a.y + g.y) * inv_tau;
        v.z = (a.z + g.z) * inv_tau;
        v.w = (a.w + g.w) * inv_tau;
        *reinterpret_cast<float4*>(&sv[c]) = v;
        lmax = fmaxf(lmax, fmaxf(fmaxf(v.x, v.y), fmaxf(v.z, v.w)));
    }
    #pragma unroll
    for (int off = 16; off; off >>= 1)
        lmax = fmaxf(lmax, __shfl_xor_sync(0xffffffffu, lmax, off));
    if (l == 0) redm[w] = lmax;
    __syncthreads();
    float bmax = redm[0];
    #pragma unroll
    for (int i = 1; i < 8; i++) bmax = fmaxf(bmax, redm[i]);

    float lsum = 0.0f;
    for (int c = tid * 4; c < C_; c += 1024) {
        float4 v = *reinterpret_cast<const float4*>(&sv[c]);
        v.x = __expf(v.x - bmax);
        v.y = __expf(v.y - bmax);
        v.z = __expf(v.z - bmax);
        v.w = __expf(v.w - bmax);
        *reinterpret_cast<float4*>(&sv[c]) = v;
        lsum += (v.x + v.y) + (v.z + v.w);
    }
    #pragma unroll
    for (int off = 16; off; off >>= 1)
        lsum += __shfl_xor_sync(0xffffffffu, lsum, off);
    if (l == 0) reds[w] = lsum;
    __syncthreads();
    float bsum = 0.0f;
    #pragma unroll
    for (int i = 0; i < 8; i++) bsum += reds[i];
    const float inv = 1.0f / bsum;

    for (int c = tid * 4; c < C_; c += 1024) {
        float4 v = *reinterpret_cast<const float4*>(&sv[c]);
        v.x *= inv; v.y *= inv; v.z *= inv; v.w *= inv;
        *reinterpret_cast<float4*>(&z[base + c]) = v;
        unsigned h0, l0, h1, l1;
        bsplit2(v.x, v.y, h0, l0);
        bsplit2(v.z, v.w, h1, l1);
        size_t u = (base + c) >> 1;
        *reinterpret_cast<uint2*>(&g_zh[u]) = make_uint2(h0, h1);
        *reinterpret_cast<uint2*>(&g_zl[u]) = make_uint2(l0, l1);
    }
}

// ============ Kernel 3: q1 partials = z @ W^T, bf16x3, cp.async pipeline ============
// grid (32 m-tiles, 2 n-tiles, 4 k-splits) = 256 CTAs = one wave at 2 CTAs/SM.
// Block 256 (8 warps: 2m x 4n; warp tile 32x32). CTA tile 64(M) x 128(N),
// K-slice 2048, chunks of 64 (4 k16-steps), 2-stage double buffer.
// stage u32: Ah[64*36]@0, Al@2304, Bh[128*36]@4608, Bl@9216; stage = 13824 u32.
#define G2_STAGE 13824
#define G2_SMEM_BYTES (2 * G2_STAGE * 4)
__global__ __launch_bounds__(256, 2) void k_gemm_cb_mma()
{
    extern __shared__ __align__(16) unsigned sm2[];
    const int m0 = blockIdx.x * 64;
    const int d0 = blockIdx.y * 128;
    const int k0 = blockIdx.z * (C_ / KSPLIT);   // 2048
    float* part = g_q1p[blockIdx.z];
    const int tid = threadIdx.x;
    const int wid = tid >> 5, lane = tid & 31;
    const int g = lane >> 2, tig = lane & 3;
    const int wm = wid & 1, wn = wid >> 1;
    const int l16 = lane & 15, lh = lane >> 4;

    float acc[2][4][4];
    #pragma unroll
    for (int i = 0; i < 2; i++)
        #pragma unroll
        for (int j = 0; j < 4; j++)
            #pragma unroll
            for (int t = 0; t < 4; t++) acc[i][j][t] = 0.0f;

    auto issue = [&](int ch, unsigned* st) {
        const size_t kc = (size_t)(k0 + ch * 64) / 2;
        #pragma unroll
        for (int j = 0; j < 4; j++) {
            int idx = tid + j * 256;
            int pl = idx >> 9, rem = idx & 511, r = rem >> 3, q = rem & 7;
            const unsigned* src = (pl ? g_zl : g_zh) + (size_t)(m0 + r) * (C_ / 2) + kc + 4 * q;
            cpa16(sptr(st + pl * 2304 + r * 36 + 4 * q), src);
        }
        #pragma unroll
        for (int j = 0; j < 8; j++) {
            int idx = tid + j * 256;
            int pl = idx >> 10, rem = idx & 1023, r = rem >> 3, q = rem & 7;
            const unsigned* src = (pl ? g_Wl : g_Wh) + (size_t)(d0 + r) * (C_ / 2) + kc + 4 * q;
            cpa16(sptr(st + 4608 + pl * 4608 + r * 36 + 4 * q), src);
        }
        asm volatile("cp.async.commit_group;" ::: "memory");
    };

    const int NCH = (C_ / KSPLIT) / 64;   // 32 chunks
    issue(0, sm2);

    for (int ch = 0; ch < NCH; ch++) {
        asm volatile("cp.async.wait_group 0;" ::: "memory");
        __syncthreads();
        if (ch + 1 < NCH) issue(ch + 1, sm2 + ((ch + 1) & 1) * G2_STAGE);

        unsigned* st = sm2 + (ch & 1) * G2_STAGE;
        unsigned* Ah = st;
        unsigned* Al = st + 2304;
        unsigned* Bh = st + 4608;
        unsigned* Bl = st + 9216;

        #pragma unroll
        for (int s = 0; s < 4; s++) {
            const int kp = s * 8 + lh * 4;
            unsigned bh[4][2], bl[4][2];
            #pragma unroll
            for (int p = 0; p < 2; p++) {
                unsigned bf[4];
                const int boff = (wn * 32 + p * 16 + l16) * 36 + kp;
                ldsm4(bf, sptr(Bh + boff));
                bh[2 * p][0] = bf[0]; bh[2 * p][1] = bf[2];
                bh[2 * p + 1][0] = bf[1]; bh[2 * p + 1][1] = bf[3];
                ldsm4(bf, sptr(Bl + boff));
                bl[2 * p][0] = bf[0]; bl[2 * p][1] = bf[2];
                bl[2 * p + 1][0] = bf[1]; bl[2 * p + 1][1] = bf[3];
            }
            unsigned ah[2][4], al[2][4];
            #pragma unroll
            for (int mf = 0; mf < 2; mf++) {
                const int aoff = (wm * 32 + mf * 16 + l16) * 36 + kp;
                ldsm4(ah[mf], sptr(Ah + aoff));
                ldsm4(al[mf], sptr(Al + aoff));
            }
            // pass-major: hh, hl, lh
            #pragma unroll
            for (int mf = 0; mf < 2; mf++)
                #pragma unroll
                for (int nf = 0; nf < 4; nf++)
                    mma16(acc[mf][nf], ah[mf], bh[nf]);
            #pragma unroll
            for (int mf = 0; mf < 2; mf++)
                #pragma unroll
                for (int nf = 0; nf < 4; nf++)
                    mma16(acc[mf][nf], ah[mf], bl[nf]);
            #pragma unroll
            for (int mf = 0; mf < 2; mf++)
                #pragma unroll
                for (int nf = 0; nf < 4; nf++)
                    mma16(acc[mf][nf], al[mf], bh[nf]);
        }
    }

    #pragma unroll
    for (int mf = 0; mf < 2; mf++) {
        int r = m0 + wm * 32 + mf * 16 + g;
        #pragma unroll
        for (int nf = 0; nf < 4; nf++) {
            int d = d0 + wn * 32 + nf * 8 + 2 * tig;
            *reinterpret_cast<float2*>(&part[(size_t)r * D_ + d]) =
                make_float2(acc[mf][nf][0], acc[mf][nf][1]);
            *reinterpret_cast<float2*>(&part[(size_t)(r + 8) * D_ + d]) =
                make_float2(acc[mf][nf][2], acc[mf][nf][3]);
        }
    }
}

// ============ Kernel 4: quantized[b,n,j] = sum_d q1[b,n,d] * pos_map[n,d,j] ============
// Fused K-split reduction: staging sums the 4 partials directly (no k_reduce).
__global__ __launch_bounds__(256) void k_posmap(
    const float* __restrict__ pm, float* __restrict__ outq)
{
    __shared__ __align__(16) float qs[256 * 36];
    const int n = blockIdx.x;
    const int j0 = blockIdx.y * 64;
    const int tid = threadIdx.x;

    for (int i = tid; i < 32 * 256; i += 256) {
        int b = i >> 8, dd = i & 255;
        size_t idx = ((size_t)b * N_ + n) * D_ + dd;
        float s = g_q1p[0][idx];
        #pragma unroll
        for (int p = 1; p < KSPLIT; p++) s += g_q1p[p][idx];
        qs[dd * 36 + b] = s;
    }
    __syncthreads();

    const int jg = tid & 31, rg = tid >> 5;
    const int j  = j0 + jg * 2, r0 = rg * 4;

    u64 acc[2][2];
    acc[0][0] = acc[0][1] = acc[1][0] = acc[1][1] = 0ull;

    #pragma unroll 4
    for (int dd = 0; dd < 256; dd++) {
        float2 wv = *reinterpret_cast<const float2*>(&pm[((size_t)n * D_ + dd) * D_ + j]);
        u64 w0 = splat2(wv.x), w1 = splat2(wv.y);
        const u64* ap = reinterpret_cast<const u64*>(&qs[dd * 36 + r0]);
        u64 a0 = ap[0], a1 = ap[1];
        ffma2(acc[0][0], a0, w0);
        ffma2(acc[0][1], a0, w1);
        ffma2(acc[1][0], a1, w0);
        ffma2(acc[1][1], a1, w1);
    }

    #pragma unroll
    for (int p = 0; p < 2; p++) {
        float2 v0 = unpack2(acc[p][0]);
        float2 v1 = unpack2(acc[p][1]);
        int rlo = r0 + 2 * p;
        *reinterpret_cast<float2*>(&outq[((size_t)rlo * N_ + n) * D_ + j]) =
            make_float2(v0.x, v1.x);
        *reinterpret_cast<float2*>(&outq[((size_t)(rlo + 1) * N_ + n) * D_ + j]) =
            make_float2(v0.y, v1.y);
    }
}

extern "C" void kernel_launch(void* const* d_in, const int* in_sizes, int n_in,
                              void* d_out, int out_size)
{
    const float* logits  = (const float*)d_in[0];  // [B,N,D]
    const float* head    = (const float*)d_in[1];  // [N,D,C]
    const float* pos_map = (const float*)d_in[2];  // [N,D,D]
    const float* cbw     = (const float*)d_in[3];  // [D,C]
    const float* gum     = (const float*)d_in[4];  // [B,N,C]
    const float* tau     = (const float*)d_in[5];  // [1]

    float* out  = (float*)d_out;
    float* outq = out;                                   // quantized [B,N,D]
    float* la   = out + (size_t)B_ * N_ * D_;            // log_alpha [B,N,C]
    float* z    = la + (size_t)B_ * N_ * C_;             // z [B,N,C]

    cudaFuncSetAttribute(k_gemm_head_mma, cudaFuncAttributeMaxDynamicSharedMemorySize,
                         G1_SMEM_BYTES);
    cudaFuncSetAttribute(k_gemm_cb_mma, cudaFuncAttributeMaxDynamicSharedMemorySize,
                         G2_SMEM_BYTES);

    // softmax split in two (independent rows) so k_gemm_cb_mma sits at ncu's
    // captured 4th launch position.
    k_gemm_head_mma<<<dim3(C_ / 256, N_ + 1), 256, G1_SMEM_BYTES>>>(logits, head, cbw, la);
    k_softmax<<<B_ * N_ / 2, 256>>>(la, gum, tau, z, 0);
    k_softmax<<<B_ * N_ / 2, 256>>>(la, gum, tau, z, B_ * N_ / 2);
    k_gemm_cb_mma<<<dim3(32, 2, KSPLIT), 256, G2_SMEM_BYTES>>>();
    k_posmap<<<dim3(N_, 4), 256>>>(pos_map, outq);
}

// round 15
// speedup vs baseline: 1.0439x; 1.0439x over previous
#include <cuda_runtime.h>
#include <cstdint>

typedef unsigned long long u64;

#define B_ 32
#define N_ 64
#define D_ 256
#define C_ 8192
#define KSPLIT 4

// Scratch (static device memory — no runtime allocation).
__device__ float g_q1p[KSPLIT][(size_t)B_ * N_ * D_]; // K-split partials, 8 MB
__device__ unsigned g_Wh[(size_t)D_ * (C_ / 2)];      // W hi bf16x2, 4 MB
__device__ unsigned g_Wl[(size_t)D_ * (C_ / 2)];      // W lo bf16x2, 4 MB
__device__ unsigned g_zh[(size_t)B_ * N_ * (C_ / 2)]; // z hi bf16x2, 32 MB
__device__ unsigned g_zl[(size_t)B_ * N_ * (C_ / 2)]; // z lo bf16x2, 32 MB

// ---------- packed f32x2 helpers (posmap) ----------
__device__ __forceinline__ u64 splat2(float x) {
    u64 r; unsigned xi = __float_as_uint(x);
    asm("mov.b64 %0, {%1, %1};" : "=l"(r) : "r"(xi));
    return r;
}
__device__ __forceinline__ void ffma2(u64 &d, u64 a, u64 b) {
    asm("fma.rn.f32x2 %0, %1, %2, %0;" : "+l"(d) : "l"(a), "l"(b));
}
__device__ __forceinline__ float2 unpack2(u64 v) {
    unsigned lo, hi;
    asm("mov.b64 {%0, %1}, %2;" : "=r"(lo), "=r"(hi) : "l"(v));
    return make_float2(__uint_as_float(lo), __uint_as_float(hi));
}

// ---------- bf16 split: (x,y) -> packed hi bf16x2 + packed lo bf16x2 ----------
__device__ __forceinline__ void bsplit2(float x, float y, unsigned &h, unsigned &l) {
    unsigned hp;
    asm("cvt.rn.bf16x2.f32 %0, %1, %2;" : "=r"(hp) : "f"(y), "f"(x));
    float hx = __uint_as_float(hp << 16);
    float hy = __uint_as_float(hp & 0xFFFF0000u);
    asm("cvt.rn.bf16x2.f32 %0, %1, %2;" : "=r"(l) : "f"(y - hy), "f"(x - hx));
    h = hp;
}

// D += A@B, m16n8k16 bf16
__device__ __forceinline__ void mma16(float* d, const unsigned* a, const unsigned* b) {
    asm volatile(
        "mma.sync.aligned.m16n8k16.row.col.f32.bf16.bf16.f32 "
        "{%0,%1,%2,%3}, {%4,%5,%6,%7}, {%8,%9}, {%0,%1,%2,%3};"
        : "+f"(d[0]), "+f"(d[1]), "+f"(d[2]), "+f"(d[3])
        : "r"(a[0]), "r"(a[1]), "r"(a[2]), "r"(a[3]), "r"(b[0]), "r"(b[1]));
}

// ---------- smem / ldmatrix / cp.async ----------
__device__ __forceinline__ unsigned sptr(const void* p) {
    return (unsigned)__cvta_generic_to_shared(p);
}
__device__ __forceinline__ void ldsm4(unsigned* r, unsigned addr) {
    asm volatile("ldmatrix.sync.aligned.m8n8.x4.shared.b16 {%0,%1,%2,%3}, [%4];"
                 : "=r"(r[0]), "=r"(r[1]), "=r"(r[2]), "=r"(r[3]) : "r"(addr));
}
__device__ __forceinline__ void ldsm4t(unsigned* r, unsigned addr) {
    asm volatile("ldmatrix.sync.aligned.m8n8.x4.trans.shared.b16 {%0,%1,%2,%3}, [%4];"
                 : "=r"(r[0]), "=r"(r[1]), "=r"(r[2]), "=r"(r[3]) : "r"(addr));
}
__device__ __forceinline__ void cpa16(unsigned dst, const void* src) {
    asm volatile("cp.async.cg.shared.global [%0], [%1], 16;" :: "r"(dst), "l"(src) : "memory");
}

// ============ Kernel 1: la[b,n,c] = sum_k logits[b,n,k] * head[n,k,c] ============
// Grid (32, 65): blockIdx.y < 64 -> GEMM tile; blockIdx.y == 64 -> W pre-split.
// GEMM: bf16 3-pass split (hh+hl+lh), pass-major MMA order, ldmatrix fragments,
// register-prefetch double-buffered staging. Block 256 (8 warps: 2m x 4n;
// warp tile 16x64). K=256, chunks of 32.
// stage u32 layout: Ah[32*20]@0, Al@640, Bh[32*132]@1280, Bl@5504; stage = 9728 u32.
#define G1_STAGE 9728
#define G1_SMEM_BYTES (2 * G1_STAGE * 4)
__global__ __launch_bounds__(256, 2) void k_gemm_head_mma(
    const float* __restrict__ logits, const float* __restrict__ head,
    const float* __restrict__ W, float* __restrict__ la)
{
    extern __shared__ __align__(16) unsigned sm1[];
    const int tid = threadIdx.x;

    if (blockIdx.y == N_) {
        // W pre-split plane: 32 CTAs x 256 thr x 64 float4 = 8 MB
        #pragma unroll 4
        for (int it = 0; it < 64; it++) {
            size_t i = (size_t)blockIdx.x * 16384 + (size_t)it * 256 + tid;
            float4 v = *reinterpret_cast<const float4*>(&W[i * 4]);
            unsigned h0, l0, h1, l1;
            bsplit2(v.x, v.y, h0, l0);
            bsplit2(v.z, v.w, h1, l1);
            g_Wh[i * 2] = h0; g_Wh[i * 2 + 1] = h1;
            g_Wl[i * 2] = l0; g_Wl[i * 2 + 1] = l1;
        }
        return;
    }

    const int n  = blockIdx.y;
    const int c0 = blockIdx.x * 256;
    const int wid = tid >> 5, lane = tid & 31;
    const int g = lane >> 2, tig = lane & 3;
    const int wm = wid & 1, wn = wid >> 1;
    const int ra = tid >> 3, qa = tid & 7;
    const int l16 = lane & 15, lh = lane >> 4;

    float acc[8][4];
    #pragma unroll
    for (int i = 0; i < 8; i++)
        #pragma unroll
        for (int j = 0; j < 4; j++) acc[i][j] = 0.0f;

    // prologue: load + stage chunk 0 into buffer 0
    {
        float4 va = *reinterpret_cast<const float4*>(
            &logits[((size_t)ra * N_ + n) * D_ + 4 * qa]);
        unsigned* Ah = sm1;
        unsigned* Al = sm1 + 640;
        unsigned* Bh = sm1 + 1280;
        unsigned* Bl = sm1 + 5504;
        unsigned h0, l0, h1, l1;
        bsplit2(va.x, va.y, h0, l0); bsplit2(va.z, va.w, h1, l1);
        *reinterpret_cast<uint2*>(&Ah[ra * 20 + 2 * qa]) = make_uint2(h0, h1);
        *reinterpret_cast<uint2*>(&Al[ra * 20 + 2 * qa]) = make_uint2(l0, l1);
        #pragma unroll
        for (int it = 0; it < 8; it++) {
            int i = tid + it * 256;
            int k = i >> 6, c4 = i & 63;
            float4 v = *reinterpret_cast<const float4*>(
                &head[((size_t)n * D_ + k) * C_ + c0 + 4 * c4]);
            bsplit2(v.x, v.y, h0, l0); bsplit2(v.z, v.w, h1, l1);
            *reinterpret_cast<uint2*>(&Bh[k * 132 + 2 * c4]) = make_uint2(h0, h1);
            *reinterpret_cast<uint2*>(&Bl[k * 132 + 2 * c4]) = make_uint2(l0, l1);
        }
    }
    __syncthreads();

    for (int ch = 0; ch < 8; ch++) {
        float4 va; float4 vb[8];
        if (ch < 7) {
            const int kb = (ch + 1) * 32;
            va = *reinterpret_cast<const float4*>(
                &logits[((size_t)ra * N_ + n) * D_ + kb + 4 * qa]);
            #pragma unroll
            for (int it = 0; it < 8; it++) {
                int i = tid + it * 256;
                int k = i >> 6, c4 = i & 63;
                vb[it] = *reinterpret_cast<const float4*>(
                    &head[((size_t)n * D_ + kb + k) * C_ + c0 + 4 * c4]);
            }
        }

        unsigned* st = sm1 + (ch & 1) * G1_STAGE;
        unsigned* Ah = st;
        unsigned* Al = st + 640;
        unsigned* Bh = st + 1280;
        unsigned* Bl = st + 5504;

        #pragma unroll
        for (int s = 0; s < 2; s++) {
            unsigned ah[4], al[4];
            const int aoff = (wm * 16 + l16) * 20 + s * 8 + lh * 4;
            ldsm4(ah, sptr(Ah + aoff));
            ldsm4(al, sptr(Al + aoff));
            unsigned bfh[4][4], bfl[4][4];
            #pragma unroll
            for (int p = 0; p < 4; p++) {
                const int boff = (s * 16 + l16) * 132 + wn * 32 + p * 8 + lh * 4;
                ldsm4t(bfh[p], sptr(Bh + boff));
                ldsm4t(bfl[p], sptr(Bl + boff));
            }
            #pragma unroll
            for (int p = 0; p < 4; p++) {
                mma16(acc[2 * p],     ah, &bfh[p][0]);
                mma16(acc[2 * p + 1], ah, &bfh[p][2]);
            }
            #pragma unroll
            for (int p = 0; p < 4; p++) {
                mma16(acc[2 * p],     ah, &bfl[p][0]);
                mma16(acc[2 * p + 1], ah, &bfl[p][2]);
            }
            #pragma unroll
            for (int p = 0; p < 4; p++) {
                mma16(acc[2 * p],     al, &bfh[p][0]);
                mma16(acc[2 * p + 1], al, &bfh[p][2]);
            }
        }

        if (ch < 7) {
            unsigned* nx = sm1 + ((ch + 1) & 1) * G1_STAGE;
            unsigned* nAh = nx;
            unsigned* nAl = nx + 640;
            unsigned* nBh = nx + 1280;
            unsigned* nBl = nx + 5504;
            unsigned h0, l0, h1, l1;
            bsplit2(va.x, va.y, h0, l0); bsplit2(va.z, va.w, h1, l1);
            *reinterpret_cast<uint2*>(&nAh[ra * 20 + 2 * qa]) = make_uint2(h0, h1);
            *reinterpret_cast<uint2*>(&nAl[ra * 20 + 2 * qa]) = make_uint2(l0, l1);
            #pragma unroll
            for (int it = 0; it < 8; it++) {
                int i = tid + it * 256;
                int k = i >> 6, c4 = i & 63;
                bsplit2(vb[it].x, vb[it].y, h0, l0);
                bsplit2(vb[it].z, vb[it].w, h1, l1);
                *reinterpret_cast<uint2*>(&nBh[k * 132 + 2 * c4]) = make_uint2(h0, h1);
                *reinterpret_cast<uint2*>(&nBl[k * 132 + 2 * c4]) = make_uint2(l0, l1);
            }
        }
        __syncthreads();
    }

    const int r = wm * 16 + g;
    #pragma unroll
    for (int nf = 0; nf < 8; nf++) {
        int c = c0 + wn * 64 + nf * 8 + 2 * tig;
        size_t b1 = ((size_t)r * N_ + n) * C_ + c;
        size_t b2 = ((size_t)(r + 8) * N_ + n) * C_ + c;
        *reinterpret_cast<float2*>(&la[b1]) = make_float2(acc[nf][0], acc[nf][1]);
        *reinterpret_cast<float2*>(&la[b2]) = make_float2(acc[nf][2], acc[nf][3]);
    }
}

// ============ Kernel 2: z = softmax((la + gum)/tau); also emit bf16 hi/lo planes ============
__global__ __launch_bounds__(256) void k_softmax(
    const float* __restrict__ la, const float* __restrict__ gum,
    const float* __restrict__ tau, float* __restrict__ z)
{
    __shared__ __align__(16) float sv[C_];
    __shared__ float redm[8];
    __shared__ float reds[8];
    const int m = blockIdx.x;
    const size_t base = (size_t)m * C_;
    const float inv_tau = 1.0f / tau[0];
    const int tid = threadIdx.x;
    const int w = tid >> 5, l = tid & 31;

    float lmax = -3.4e38f;
    for (int c = tid * 4; c < C_; c += 1024) {
        float4 a = *reinterpret_cast<const float4*>(&la[base + c]);
        float4 g = *reinterpret_cast<const float4*>(&gum[base + c]);
        float4 v;
        v.x = (a.x + g.x) * inv_tau;
        v.y = (a.y + g.y) * inv_tau;
        v.z = (a.z + g.z) * inv_tau;
        v.w = (a.w + g.w) * inv_tau;
        *reinterpret_cast<float4*>(&sv[c]) = v;
        lmax = fmaxf(lmax, fmaxf(fmaxf(v.x, v.y), fmaxf(v.z, v.w)));
    }
    #pragma unroll
    for (int off = 16; off; off >>= 1)
        lmax = fmaxf(lmax, __shfl_xor_sync(0xffffffffu, lmax, off));
    if (l == 0) redm[w] = lmax;
    __syncthreads();
    float bmax = redm[0];
    #pragma unroll
    for (int i = 1; i < 8; i++) bmax = fmaxf(bmax, redm[i]);

    float lsum = 0.0f;
    for (int c = tid * 4; c < C_; c += 1024) {
        float4 v = *reinterpret_cast<const float4*>(&sv[c]);
        v.x = __expf(v.x - bmax);
        v.y = __expf(v.y - bmax);
        v.z = __expf(v.z - bmax);
        v.w = __expf(v.w - bmax);
        *reinterpret_cast<float4*>(&sv[c]) = v;
        lsum += (v.x + v.y) + (v.z + v.w);
    }
    #pragma unroll
    for (int off = 16; off; off >>= 1)
        lsum += __shfl_xor_sync(0xffffffffu, lsum, off);
    if (l == 0) reds[w] = lsum;
    __syncthreads();
    float bsum = 0.0f;
    #pragma unroll
    for (int i = 0; i < 8; i++) bsum += reds[i];
    const float inv = 1.0f / bsum;

    for (int c = tid * 4; c < C_; c += 1024) {
        float4 v = *reinterpret_cast<const float4*>(&sv[c]);
        v.x *= inv; v.y *= inv; v.z *= inv; v.w *= inv;
        *reinterpret_cast<float4*>(&z[base + c]) = v;
        unsigned h0, l0, h1, l1;
        bsplit2(v.x, v.y, h0, l0);
        bsplit2(v.z, v.w, h1, l1);
        size_t u = (base + c) >> 1;
        *reinterpret_cast<uint2*>(&g_zh[u]) = make_uint2(h0, h1);
        *reinterpret_cast<uint2*>(&g_zl[u]) = make_uint2(l0, l1);
    }
}

// ============ Kernel 3: q1 partials = z @ W^T, bf16x3, cp.async pipeline ============
// grid (32 m-tiles, 2 n-tiles, 4 k-splits) = 256 CTAs, block 256
// (8 warps: 2m x 4n; warp tile 32x32). CTA tile 64(M) x 128(N), K-slice 2048,
// chunks of 64 (4 k16-steps), 2-stage double buffer, 2 CTAs/SM.
// stage u32: Ah[64*36]@0, Al@2304, Bh[128*36]@4608, Bl@9216; stage = 13824 u32.
#define G2_STAGE 13824
#define G2_SMEM_BYTES (2 * G2_STAGE * 4)
__global__ __launch_bounds__(256, 2) void k_gemm_cb_mma()
{
    extern __shared__ __align__(16) unsigned sm2[];
    const int m0 = blockIdx.x * 64;
    const int d0 = blockIdx.y * 128;
    const int k0 = blockIdx.z * (C_ / KSPLIT);   // 2048
    float* part = g_q1p[blockIdx.z];
    const int tid = threadIdx.x;
    const int wid = tid >> 5, lane = tid & 31;
    const int g = lane >> 2, tig = lane & 3;
    const int wm = wid & 1, wn = wid >> 1;
    const int l16 = lane & 15, lh = lane >> 4;

    float acc[2][4][4];
    #pragma unroll
    for (int i = 0; i < 2; i++)
        #pragma unroll
        for (int j = 0; j < 4; j++)
            #pragma unroll
            for (int t = 0; t < 4; t++) acc[i][j][t] = 0.0f;

    auto issue = [&](int ch, unsigned* st) {
        const size_t kc = (size_t)(k0 + ch * 64) / 2;
        #pragma unroll
        for (int j = 0; j < 4; j++) {
            int idx = tid + j * 256;
            int pl = idx >> 9, rem = idx & 511, r = rem >> 3, q = rem & 7;
            const unsigned* src = (pl ? g_zl : g_zh) + (size_t)(m0 + r) * (C_ / 2) + kc + 4 * q;
            cpa16(sptr(st + pl * 2304 + r * 36 + 4 * q), src);
        }
        #pragma unroll
        for (int j = 0; j < 8; j++) {
            int idx = tid + j * 256;
            int pl = idx >> 10, rem = idx & 1023, r = rem >> 3, q = rem & 7;
            const unsigned* src = (pl ? g_Wl : g_Wh) + (size_t)(d0 + r) * (C_ / 2) + kc + 4 * q;
            cpa16(sptr(st + 4608 + pl * 4608 + r * 36 + 4 * q), src);
        }
        asm volatile("cp.async.commit_group;" ::: "memory");
    };

    const int NCH = (C_ / KSPLIT) / 64;   // 32 chunks
    issue(0, sm2);

    for (int ch = 0; ch < NCH; ch++) {
        asm volatile("cp.async.wait_group 0;" ::: "memory");
        __syncthreads();
        if (ch + 1 < NCH) issue(ch + 1, sm2 + ((ch + 1) & 1) * G2_STAGE);

        unsigned* st = sm2 + (ch & 1) * G2_STAGE;
        unsigned* Ah = st;
        unsigned* Al = st + 2304;
        unsigned* Bh = st + 4608;
        unsigned* Bl = st + 9216;

        #pragma unroll
        for (int s = 0; s < 4; s++) {
            const int kp = s * 8 + lh * 4;
            unsigned bh[4][2], bl[4][2];
            #pragma unroll
            for (int p = 0; p < 2; p++) {
                unsigned bf[4];
                const int boff = (wn * 32 + p * 16 + l16) * 36 + kp;
                ldsm4(bf, sptr(Bh + boff));
                bh[2 * p][0] = bf[0]; bh[2 * p][1] = bf[2];
                bh[2 * p + 1][0] = bf[1]; bh[2 * p + 1][1] = bf[3];
                ldsm4(bf, sptr(Bl + boff));
                bl[2 * p][0] = bf[0]; bl[2 * p][1] = bf[2];
                bl[2 * p + 1][0] = bf[1]; bl[2 * p + 1][1] = bf[3];
            }
            unsigned ah[2][4], al[2][4];
            #pragma unroll
            for (int mf = 0; mf < 2; mf++) {
                const int aoff = (wm * 32 + mf * 16 + l16) * 36 + kp;
                ldsm4(ah[mf], sptr(Ah + aoff));
                ldsm4(al[mf], sptr(Al + aoff));
            }
            // pass-major: hh, hl, lh
            #pragma unroll
            for (int mf = 0; mf < 2; mf++)
                #pragma unroll
                for (int nf = 0; nf < 4; nf++)
                    mma16(acc[mf][nf], ah[mf], bh[nf]);
            #pragma unroll
            for (int mf = 0; mf < 2; mf++)
                #pragma unroll
                for (int nf = 0; nf < 4; nf++)
                    mma16(acc[mf][nf], ah[mf], bl[nf]);
            #pragma unroll
            for (int mf = 0; mf < 2; mf++)
                #pragma unroll
                for (int nf = 0; nf < 4; nf++)
                    mma16(acc[mf][nf], al[mf], bh[nf]);
        }
    }

    #pragma unroll
    for (int mf = 0; mf < 2; mf++) {
        int r = m0 + wm * 32 + mf * 16 + g;
        #pragma unroll
        for (int nf = 0; nf < 4; nf++) {
            int d = d0 + wn * 32 + nf * 8 + 2 * tig;
            *reinterpret_cast<float2*>(&part[(size_t)r * D_ + d]) =
                make_float2(acc[mf][nf][0], acc[mf][nf][1]);
            *reinterpret_cast<float2*>(&part[(size_t)(r + 8) * D_ + d]) =
                make_float2(acc[mf][nf][2], acc[mf][nf][3]);
        }
    }
}

// ============ Kernel 4: quantized[b,n,j] = sum_d q1[b,n,d] * pos_map[n,d,j] ============
// Fused K-split reduction: staging sums the 4 partials directly.
__global__ __launch_bounds__(256) void k_posmap(
    const float* __restrict__ pm, float* __restrict__ outq)
{
    __shared__ __align__(16) float qs[256 * 36];
    const int n = blockIdx.x;
    const int j0 = blockIdx.y * 64;
    const int tid = threadIdx.x;

    for (int i = tid; i < 32 * 256; i += 256) {
        int b = i >> 8, dd = i & 255;
        size_t idx = ((size_t)b * N_ + n) * D_ + dd;
        float s = g_q1p[0][idx];
        #pragma unroll
        for (int p = 1; p < KSPLIT; p++) s += g_q1p[p][idx];
        qs[dd * 36 + b] = s;
    }
    __syncthreads();

    const int jg = tid & 31, rg = tid >> 5;
    const int j  = j0 + jg * 2, r0 = rg * 4;

    u64 acc[2][2];
    acc[0][0] = acc[0][1] = acc[1][0] = acc[1][1] = 0ull;

    #pragma unroll 4
    for (int dd = 0; dd < 256; dd++) {
        float2 wv = *reinterpret_cast<const float2*>(&pm[((size_t)n * D_ + dd) * D_ + j]);
        u64 w0 = splat2(wv.x), w1 = splat2(wv.y);
        const u64* ap = reinterpret_cast<const u64*>(&qs[dd * 36 + r0]);
        u64 a0 = ap[0], a1 = ap[1];
        ffma2(acc[0][0], a0, w0);
        ffma2(acc[0][1], a0, w1);
        ffma2(acc[1][0], a1, w0);
        ffma2(acc[1][1], a1, w1);
    }

    #pragma unroll
    for (int p = 0; p < 2; p++) {
        float2 v0 = unpack2(acc[p][0]);
        float2 v1 = unpack2(acc[p][1]);
        int rlo = r0 + 2 * p;
        *reinterpret_cast<float2*>(&outq[((size_t)rlo * N_ + n) * D_ + j]) =
            make_float2(v0.x, v1.x);
        *reinterpret_cast<float2*>(&outq[((size_t)(rlo + 1) * N_ + n) * D_ + j]) =
            make_float2(v0.y, v1.y);
    }
}

extern "C" void kernel_launch(void* const* d_in, const int* in_sizes, int n_in,
                              void* d_out, int out_size)
{
    const float* logits  = (const float*)d_in[0];  // [B,N,D]
    const float* head    = (const float*)d_in[1];  // [N,D,C]
    const float* pos_map = (const float*)d_in[2];  // [N,D,D]
    const float* cbw     = (const float*)d_in[3];  // [D,C]
    const float* gum     = (const float*)d_in[4];  // [B,N,C]
    const float* tau     = (const float*)d_in[5];  // [1]

    float* out  = (float*)d_out;
    float* outq = out;                                   // quantized [B,N,D]
    float* la   = out + (size_t)B_ * N_ * D_;            // log_alpha [B,N,C]
    float* z    = la + (size_t)B_ * N_ * C_;             // z [B,N,C]

    cudaFuncSetAttribute(k_gemm_head_mma, cudaFuncAttributeMaxDynamicSharedMemorySize,
                         G1_SMEM_BYTES);
    cudaFuncSetAttribute(k_gemm_cb_mma, cudaFuncAttributeMaxDynamicSharedMemorySize,
                         G2_SMEM_BYTES);

    k_gemm_head_mma<<<dim3(C_ / 256, N_ + 1), 256, G1_SMEM_BYTES>>>(logits, head, cbw, la);
    k_softmax<<<B_ * N_, 256>>>(la, gum, tau, z);
    k_gemm_cb_mma<<<dim3(32, 2, KSPLIT), 256, G2_SMEM_BYTES>>>();
    k_posmap<<<dim3(N_, 4), 256>>>(pos_map, outq);
}